// round 4
// baseline (speedup 1.0000x reference)
#include <cuda_runtime.h>
#include <cuda_bf16.h>
#include <cstdint>

#define NN   32768
#define LLn  32
#define EEn  1024
#define VVn  2048
#define FFn  8
#define HUU  128
#define D0C  512
#define D1RC 129
#define D1EC 640
#define PPn  320
#define SIGL 584
#define FINALC 9344
#define EPSF 1e-5f
#define DT0  (1.0f/51360.0f)

#define ST_X   0
#define ST_Y1  2
#define ST_Y2  2050
#define ST_Z   4098
#define ST_TOT 4114

__device__ double g_st[ST_TOT];
__device__ float  g_A[(size_t)FFn * NN * HUU];
__device__ float  g_B[(size_t)FFn * NN * HUU];
__device__ float  g_z[FFn * NN];
__device__ float  g_evs[FFn * NN];
__device__ float  g_fv[LLn * FFn * VVn];
__device__ float  g_x[LLn * FINALC];
__device__ float  g_fz[LLn];

__global__ void k_zero() {
    int i = blockIdx.x * 256 + threadIdx.x;
    if (i < ST_TOT) g_st[i] = 0.0;
}

__global__ void k_xstats(const float* __restrict__ x) {
    __shared__ float rs[256], rq[256];
    int idx = blockIdx.x * 256 + threadIdx.x;
    float v = x[idx];
    rs[threadIdx.x] = v; rq[threadIdx.x] = v * v;
    __syncthreads();
    for (int o = 128; o > 0; o >>= 1) {
        if (threadIdx.x < o) { rs[threadIdx.x] += rs[threadIdx.x + o]; rq[threadIdx.x] += rq[threadIdx.x + o]; }
        __syncthreads();
    }
    if (threadIdx.x == 0) {
        atomicAdd(&g_st[ST_X + 0], (double)rs[0]);
        atomicAdd(&g_st[ST_X + 1], (double)rq[0]);
    }
}

// h0 = relu(BN(Win*x+bin)); BN analytic: pre-act = w*x+b -> mean=w*mu+b, var=w^2*var_x
__global__ void k_layer1(const float* __restrict__ x, const float* __restrict__ Win,
                         const float* __restrict__ gin, const float* __restrict__ bein) {
    size_t idx = (size_t)blockIdx.x * 256 + threadIdx.x;
    int j = (int)(idx & 127);
    int n = (int)((idx >> 7) & 32767);
    int f = (int)(idx >> 22);
    double mud = g_st[ST_X] / (double)NN;
    float mu  = (float)mud;
    float var = (float)(g_st[ST_X + 1] / (double)NN - mud * mud);
    float w = Win[f * HUU + j];
    float sc = gin[f * HUU + j] * rsqrtf(w * w * var + EPSF);
    float val = w * (x[n] - mu) * sc + bein[f * HUU + j];
    g_A[idx] = fmaxf(val, 0.f);
}

// GEMM Y[f][n][j] = sum_k act(X[f][n][k]) * W[f][layer][j][k] + b; stats of Y.
__global__ __launch_bounds__(256) void k_gemm(
        const float* __restrict__ Wh, const float* __restrict__ bh,
        const float* __restrict__ gh, const float* __restrict__ betah,
        int layer, int bn_in) {
    __shared__ __align__(16) float As[16][132];
    __shared__ __align__(16) float Bs[16][132];
    __shared__ float s_scale[128], s_shift[128], s_sum[128], s_sq[128];
    int f  = blockIdx.z;
    int r0 = blockIdx.x * 128;
    int tid = threadIdx.x;
    const float* X = (layer == 0) ? g_A : g_B;
    float*       Y = (layer == 0) ? g_B : g_A;
    double* out_st = g_st + ((layer == 0) ? ST_Y1 : ST_Y2);
    const float* Xf   = X + (size_t)f * NN * HUU;
    const float* W    = Wh + ((size_t)(f * 2 + layer)) * HUU * HUU;
    const float* bias = bh + (f * 2 + layer) * HUU;

    if (tid < 128) {
        s_sum[tid] = 0.f; s_sq[tid] = 0.f;
        if (bn_in) {
            const double* ist = g_st + ST_Y1;
            double mu  = ist[(f * HUU + tid) * 2 + 0] / (double)NN;
            double var = ist[(f * HUU + tid) * 2 + 1] / (double)NN - mu * mu;
            float sc = gh[(f * 2 + 0) * HUU + tid] * rsqrtf((float)var + EPSF);
            s_scale[tid] = sc;
            s_shift[tid] = betah[(f * 2 + 0) * HUU + tid] - (float)mu * sc;
        } else { s_scale[tid] = 1.f; s_shift[tid] = 0.f; }
    }
    __syncthreads();

    float acc[8][8];
#pragma unroll
    for (int r = 0; r < 8; r++)
#pragma unroll
        for (int c = 0; c < 8; c++) acc[r][c] = 0.f;

    int tx = tid & 15, ty = tid >> 4;
    for (int kk = 0; kk < 128; kk += 16) {
#pragma unroll
        for (int s = 0; s < 2; s++) {
            int fid = tid + s * 256;
            int row = fid >> 2;
            int kq  = (fid & 3) * 4;
            float4 v  = *(const float4*)(Xf + (size_t)(r0 + row) * HUU + kk + kq);
            float4 w4 = *(const float4*)(W + (size_t)row * HUU + kk + kq);
            if (bn_in) {
                v.x = fmaxf(v.x * s_scale[kk + kq + 0] + s_shift[kk + kq + 0], 0.f);
                v.y = fmaxf(v.y * s_scale[kk + kq + 1] + s_shift[kk + kq + 1], 0.f);
                v.z = fmaxf(v.z * s_scale[kk + kq + 2] + s_shift[kk + kq + 2], 0.f);
                v.w = fmaxf(v.w * s_scale[kk + kq + 3] + s_shift[kk + kq + 3], 0.f);
            }
            As[kq + 0][row] = v.x;  As[kq + 1][row] = v.y;
            As[kq + 2][row] = v.z;  As[kq + 3][row] = v.w;
            Bs[kq + 0][row] = w4.x; Bs[kq + 1][row] = w4.y;
            Bs[kq + 2][row] = w4.z; Bs[kq + 3][row] = w4.w;
        }
        __syncthreads();
#pragma unroll
        for (int k = 0; k < 16; k++) {
            float a[8], b[8];
            *(float4*)(a)     = *(const float4*)&As[k][ty * 8];
            *(float4*)(a + 4) = *(const float4*)&As[k][ty * 8 + 4];
            *(float4*)(b)     = *(const float4*)&Bs[k][tx * 8];
            *(float4*)(b + 4) = *(const float4*)&Bs[k][tx * 8 + 4];
#pragma unroll
            for (int r = 0; r < 8; r++)
#pragma unroll
                for (int c = 0; c < 8; c++) acc[r][c] += a[r] * b[c];
        }
        __syncthreads();
    }

    float lsum[8], lsq[8], bcol[8];
#pragma unroll
    for (int c = 0; c < 8; c++) { lsum[c] = 0.f; lsq[c] = 0.f; bcol[c] = bias[tx * 8 + c]; }
#pragma unroll
    for (int r = 0; r < 8; r++) {
        int row = r0 + ty * 8 + r;
        float y[8];
#pragma unroll
        for (int c = 0; c < 8; c++) {
            y[c] = acc[r][c] + bcol[c];
            lsum[c] += y[c]; lsq[c] += y[c] * y[c];
        }
        float* dst = Y + ((size_t)f * NN + row) * HUU + tx * 8;
        *(float4*)(dst)     = *(float4*)(y);
        *(float4*)(dst + 4) = *(float4*)(y + 4);
    }
#pragma unroll
    for (int c = 0; c < 8; c++) {
        atomicAdd(&s_sum[tx * 8 + c], lsum[c]);
        atomicAdd(&s_sq[tx * 8 + c],  lsq[c]);
    }
    __syncthreads();
    if (tid < 128) {
        atomicAdd(&out_st[(f * HUU + tid) * 2 + 0], (double)s_sum[tid]);
        atomicAdd(&out_st[(f * HUU + tid) * 2 + 1], (double)s_sq[tid]);
    }
}

__global__ __launch_bounds__(256) void k_out(
        const float* __restrict__ gh, const float* __restrict__ betah,
        const float* __restrict__ Wout, const float* __restrict__ bout) {
    __shared__ float ssc[128], ssh[128], sw[128], rs[256], rq[256];
    int f = blockIdx.y, tid = threadIdx.x;
    if (tid < 128) {
        double mu  = g_st[ST_Y2 + (f * HUU + tid) * 2 + 0] / (double)NN;
        double var = g_st[ST_Y2 + (f * HUU + tid) * 2 + 1] / (double)NN - mu * mu;
        float sc = gh[(f * 2 + 1) * HUU + tid] * rsqrtf((float)var + EPSF);
        ssc[tid] = sc;
        ssh[tid] = betah[(f * 2 + 1) * HUU + tid] - (float)mu * sc;
        sw[tid]  = Wout[f * HUU + tid];
    }
    __syncthreads();
    int n = blockIdx.x * 256 + tid;
    const float* row = g_A + ((size_t)f * NN + n) * HUU;
    float acc = 0.f;
#pragma unroll 8
    for (int k = 0; k < 128; k += 4) {
        float4 v = *(const float4*)(row + k);
        acc += fmaxf(v.x * ssc[k + 0] + ssh[k + 0], 0.f) * sw[k + 0];
        acc += fmaxf(v.y * ssc[k + 1] + ssh[k + 1], 0.f) * sw[k + 1];
        acc += fmaxf(v.z * ssc[k + 2] + ssh[k + 2], 0.f) * sw[k + 2];
        acc += fmaxf(v.w * ssc[k + 3] + ssh[k + 3], 0.f) * sw[k + 3];
    }
    float zv = acc + bout[f];
    g_z[f * NN + n] = zv;
    rs[tid] = zv; rq[tid] = zv * zv;
    __syncthreads();
    for (int o = 128; o > 0; o >>= 1) {
        if (tid < o) { rs[tid] += rs[tid + o]; rq[tid] += rq[tid + o]; }
        __syncthreads();
    }
    if (tid == 0) {
        atomicAdd(&g_st[ST_Z + f * 2 + 0], (double)rs[0]);
        atomicAdd(&g_st[ST_Z + f * 2 + 1], (double)rq[0]);
    }
}

__global__ void k_evs(const float* __restrict__ gout, const float* __restrict__ betaout) {
    int idx = blockIdx.x * 256 + threadIdx.x;
    int f = idx >> 15;
    double mu  = g_st[ST_Z + f * 2 + 0] / (double)NN;
    double var = g_st[ST_Z + f * 2 + 1] / (double)NN - mu * mu;
    float sc = gout[f] * rsqrtf((float)var + EPSF);
    g_evs[idx] = fmaxf((g_z[idx] - (float)mu) * sc + betaout[f], 0.f);
}

__global__ __launch_bounds__(256) void k_einsum(const float* __restrict__ eig) {
    __shared__ __align__(16) float sh[EEn * FFn];
    int l = blockIdx.y;
    int w = threadIdx.x >> 5, lane = threadIdx.x & 31;
    for (int e = lane; e < EEn; e += 32)
        sh[e * FFn + w] = g_evs[(size_t)w * NN + l * EEn + e];
    __syncthreads();
    int v = blockIdx.x * 256 + threadIdx.x;
    const float* col = eig + (size_t)l * EEn * VVn + v;
    float acc[8] = {0,0,0,0,0,0,0,0};
#pragma unroll 4
    for (int e = 0; e < EEn; e++) {
        float ev = col[(size_t)e * VVn];
        float4 a = *(const float4*)(sh + e * FFn);
        float4 b = *(const float4*)(sh + e * FFn + 4);
        acc[0] += a.x * ev; acc[1] += a.y * ev; acc[2] += a.z * ev; acc[3] += a.w * ev;
        acc[4] += b.x * ev; acc[5] += b.y * ev; acc[6] += b.z * ev; acc[7] += b.w * ev;
    }
#pragma unroll
    for (int f = 0; f < 8; f++)
        g_fv[((size_t)(l * FFn + f)) * VVn + v] = acc[f];
}

// One block per diagram (l,f,which). Sort 7 projections, then level-3 signature.
__global__ __launch_bounds__(512) void k_diag(
        const int* __restrict__ dgm0, const int* __restrict__ dgm1rel,
        const int* __restrict__ dgm1ext,
        const float* __restrict__ Wproj, const float* __restrict__ bproj) {
    __shared__ float s_srt[7 * 512];
    __shared__ float dxT[8][329];
    __shared__ float s_un[640];
    int d = blockIdx.x;
    int which = d & 1, f = (d >> 1) & 7, l = d >> 4;
    int tid = threadIdx.x;
    int lf = l * FFn + f;
    const float* fvrow = g_fv + (size_t)lf * VVn;
    const float INF = __int_as_float(0x7f800000);

    for (int i = tid; i < 640; i += 512) {
        int col;
        if (which == 0)
            col = (i < 512) ? dgm0[lf * D0C + i] : dgm1rel[lf * D1RC + (640 - i)];
        else
            col = dgm1ext[lf * D1EC + i];
        s_un[i] = fvrow[col];
    }
    __syncthreads();
    for (int t2 = tid; t2 < 7 * 512; t2 += 512) {
        int s = t2 >> 9, p = t2 & 511;
        float v = INF;
        if (p < PPn)
            v = s_un[2 * p] * Wproj[2 * s] + s_un[2 * p + 1] * Wproj[2 * s + 1] + bproj[s];
        s_srt[t2] = v;
    }
    // bitonic ascending, 7 rows of 512
    for (int kk = 2; kk <= 512; kk <<= 1) {
        for (int jj = kk >> 1; jj > 0; jj >>= 1) {
            __syncthreads();
            for (int t2 = tid; t2 < 7 * 256; t2 += 512) {
                int row = t2 >> 8, q = t2 & 255;
                int i1 = ((q & ~(jj - 1)) << 1) | (q & (jj - 1));
                int i2 = i1 | jj;
                float* arr = s_srt + (row << 9);
                float a = arr[i1], b = arr[i2];
                if ((a > b) == ((i1 & kk) == 0)) { arr[i1] = b; arr[i2] = a; }
            }
        }
    }
    __syncthreads();
    // dx: dim0 = time (constant), dims 1..7 from sorted rows
    for (int t2 = tid; t2 < 8 * 319; t2 += 512) {
        int dd = t2 / 319, m = t2 % 319;
        dxT[dd][m] = (dd == 0) ? DT0 : (s_srt[(dd - 1) * 512 + m + 1] - s_srt[(dd - 1) * 512 + m]);
    }
    __syncthreads();

    int i = tid >> 6, j = (tid >> 3) & 7, k = tid & 7;
    float x0 = (i == 0) ? 0.f : s_srt[(i - 1) * 512];
    const float* si_row = (i == 0) ? (const float*)0 : (s_srt + (i - 1) * 512);
    float acc2 = 0.f, acc3 = 0.f;
#pragma unroll 1
    for (int m = 0; m < 319; m++) {
        float dxi = dxT[i][m], dxj = dxT[j][m], dxk = dxT[k][m];
        float s1i = (i == 0) ? ((float)m * DT0) : (si_row[m] - x0);
        float t12 = s1i * dxj;
        acc3 += (acc2 + 0.5f * t12 + (1.0f / 6.0f) * dxi * dxj) * dxk;
        acc2 += t12 + 0.5f * dxi * dxj;
    }

    float* outp = g_x + (size_t)l * FINALC + f * (2 * SIGL) + which * SIGL;
    outp[72 + tid] = acc3;
    if (k == 0) outp[8 + i * 8 + j] = acc2;
    if (tid < 8) {
        float s1;
        if (tid == 0) s1 = 319.f * DT0;
        else s1 = s_srt[(tid - 1) * 512 + 319] - s_srt[(tid - 1) * 512];
        outp[tid] = s1;
    }
}

__global__ void k_final1(const float* __restrict__ Wfin, const float* __restrict__ bfin) {
    __shared__ float rs[256];
    int l = blockIdx.x, tid = threadIdx.x;
    float acc = 0.f;
    for (int idx = tid; idx < FINALC; idx += 256)
        acc += g_x[(size_t)l * FINALC + idx] * Wfin[idx];
    rs[tid] = acc;
    __syncthreads();
    for (int o = 128; o > 0; o >>= 1) {
        if (tid < o) rs[tid] += rs[tid + o];
        __syncthreads();
    }
    if (tid == 0) g_fz[l] = rs[0] + bfin[0];
}

__global__ void k_final2(const float* __restrict__ gfin, const float* __restrict__ befin,
                         float* __restrict__ out) {
    int tid = threadIdx.x;
    float z = g_fz[tid];
    float s = z, q = z * z;
#pragma unroll
    for (int o = 16; o > 0; o >>= 1) {
        s += __shfl_xor_sync(0xffffffff, s, o);
        q += __shfl_xor_sync(0xffffffff, q, o);
    }
    float mu = s / 32.f, var = q / 32.f - mu * mu;
    out[tid] = (z - mu) * rsqrtf(var + EPSF) * gfin[0] + befin[0];
}

extern "C" void kernel_launch(void* const* d_in, const int* in_sizes, int n_in,
                              void* d_out, int out_size) {
    const float* eigenvalues = (const float*)d_in[0];
    const float* eigvec      = (const float*)d_in[1];
    const int*   dgm0        = (const int*)d_in[2];
    const int*   dgm1rel     = (const int*)d_in[3];
    const int*   dgm1ext     = (const int*)d_in[4];
    const float* Win    = (const float*)d_in[5];
    const float* gin    = (const float*)d_in[7];
    const float* bein   = (const float*)d_in[8];
    const float* Wh     = (const float*)d_in[9];
    const float* bh     = (const float*)d_in[10];
    const float* gh     = (const float*)d_in[11];
    const float* betah  = (const float*)d_in[12];
    const float* Wout   = (const float*)d_in[13];
    const float* bout   = (const float*)d_in[14];
    const float* gout   = (const float*)d_in[15];
    const float* betaout= (const float*)d_in[16];
    const float* Wproj  = (const float*)d_in[17];
    const float* bproj  = (const float*)d_in[18];
    const float* Wfin   = (const float*)d_in[19];
    const float* bfin   = (const float*)d_in[20];
    const float* gfin   = (const float*)d_in[21];
    const float* befin  = (const float*)d_in[22];
    float* out = (float*)d_out;

    k_zero<<<17, 256>>>();
    k_xstats<<<128, 256>>>(eigenvalues);
    k_layer1<<<131072, 256>>>(eigenvalues, Win, gin, bein);
    k_gemm<<<dim3(256, 1, 8), 256>>>(Wh, bh, gh, betah, 0, 0);
    k_gemm<<<dim3(256, 1, 8), 256>>>(Wh, bh, gh, betah, 1, 1);
    k_out<<<dim3(128, 8), 256>>>(gh, betah, Wout, bout);
    k_evs<<<1024, 256>>>(gout, betaout);
    k_einsum<<<dim3(8, 32), 256>>>(eigvec);
    k_diag<<<512, 512>>>(dgm0, dgm1rel, dgm1ext, Wproj, bproj);
    k_final1<<<32, 256>>>(Wfin, bfin);
    k_final2<<<1, 32>>>(gfin, befin, out);
}

// round 6
// speedup vs baseline: 1.5853x; 1.5853x over previous
#include <cuda_runtime.h>
#include <cuda_bf16.h>
#include <cstdint>

#define NN   32768
#define LLn  32
#define EEn  1024
#define VVn  2048
#define FFn  8
#define HUU  128
#define D0C  512
#define D1RC 129
#define D1EC 640
#define PPn  320
#define SIGL 584
#define FINALC 9344
#define EPSF 1e-5f
#define DT0  (1.0f/51360.0f)

#define ST_X   0
#define ST_Y1  2
#define ST_Y2  2050
#define ST_Z   4098
#define ST_TOT 4114

__device__ double g_st[ST_TOT];
__device__ float  g_A[(size_t)FFn * NN * HUU];
__device__ float  g_B[(size_t)FFn * NN * HUU];
__device__ float  g_z[FFn * NN];
__device__ float  g_zaff[FFn * 2];
__device__ float  g_fv[LLn * FFn * VVn];
__device__ float  g_x[LLn * FINALC];
__device__ float  g_fz[LLn];

__global__ void k_zero() {
    int i = blockIdx.x * 256 + threadIdx.x;
    if (i < LLn * FFn * VVn) g_fv[i] = 0.f;
    if (i < ST_TOT) g_st[i] = 0.0;
}

__global__ void k_xstats(const float* __restrict__ x) {
    __shared__ float rs[256], rq[256];
    int idx = blockIdx.x * 256 + threadIdx.x;
    float v = x[idx];
    rs[threadIdx.x] = v; rq[threadIdx.x] = v * v;
    __syncthreads();
    for (int o = 128; o > 0; o >>= 1) {
        if (threadIdx.x < o) { rs[threadIdx.x] += rs[threadIdx.x + o]; rq[threadIdx.x] += rq[threadIdx.x + o]; }
        __syncthreads();
    }
    if (threadIdx.x == 0) {
        atomicAdd(&g_st[ST_X + 0], (double)rs[0]);
        atomicAdd(&g_st[ST_X + 1], (double)rq[0]);
    }
}

// GEMM: Y[f][n][j] = sum_k act(k,n) * W[f][layer][j][k] + b; batch stats of Y.
// mode 0: act = relu(x[n]*scale_k + shift_k)   (fused input layer, scalar x)
// mode 1: act = relu(BN(g_B[f][n][k]))         (hidden layer)
__global__ __launch_bounds__(256) void k_gemm(
        const float* __restrict__ x,
        const float* __restrict__ Win, const float* __restrict__ gin,
        const float* __restrict__ bein,
        const float* __restrict__ Wh, const float* __restrict__ bh,
        const float* __restrict__ gh, const float* __restrict__ betah,
        int layer, int mode) {
    __shared__ __align__(16) float As[16][132];
    __shared__ __align__(16) float Bs[16][132];
    __shared__ float s_scale[128], s_shift[128], s_sum[128], s_sq[128];
    __shared__ float s_x[128];
    int f  = blockIdx.z;
    int r0 = blockIdx.x * 128;
    int tid = threadIdx.x;
    float*  Y      = (layer == 0) ? g_B : g_A;
    double* out_st = g_st + ((layer == 0) ? ST_Y1 : ST_Y2);
    const float* Xf   = g_B + (size_t)f * NN * HUU;
    const float* W    = Wh + ((size_t)(f * 2 + layer)) * HUU * HUU;
    const float* bias = bh + (f * 2 + layer) * HUU;

    if (tid < 128) {
        s_sum[tid] = 0.f; s_sq[tid] = 0.f;
        if (mode == 0) {
            double mud = g_st[ST_X] / (double)NN;
            float mux  = (float)mud;
            float varx = (float)(g_st[ST_X + 1] / (double)NN - mud * mud);
            float w  = Win[f * HUU + tid];
            float sc = gin[f * HUU + tid] * rsqrtf(w * w * varx + EPSF);
            s_scale[tid] = w * sc;
            s_shift[tid] = bein[f * HUU + tid] - mux * w * sc;
            s_x[tid] = x[r0 + tid];
        } else {
            const double* ist = g_st + ST_Y1;
            double mu  = ist[(f * HUU + tid) * 2 + 0] / (double)NN;
            double var = ist[(f * HUU + tid) * 2 + 1] / (double)NN - mu * mu;
            float sc = gh[(f * 2 + 0) * HUU + tid] * rsqrtf((float)var + EPSF);
            s_scale[tid] = sc;
            s_shift[tid] = betah[(f * 2 + 0) * HUU + tid] - (float)mu * sc;
        }
    }
    __syncthreads();

    unsigned long long acc[8][4];
#pragma unroll
    for (int r = 0; r < 8; r++)
#pragma unroll
        for (int c = 0; c < 4; c++) acc[r][c] = 0ull;

    int tx = tid & 15, ty = tid >> 4;
    for (int kk = 0; kk < 128; kk += 16) {
#pragma unroll
        for (int s = 0; s < 2; s++) {
            int fid = tid + s * 256;
            int row = fid >> 2;
            int kq  = (fid & 3) * 4;
            float4 w4 = *(const float4*)(W + (size_t)row * HUU + kk + kq);
            float4 v;
            if (mode == 0) {
                float xr = s_x[row];
                v.x = fmaxf(xr * s_scale[kk + kq + 0] + s_shift[kk + kq + 0], 0.f);
                v.y = fmaxf(xr * s_scale[kk + kq + 1] + s_shift[kk + kq + 1], 0.f);
                v.z = fmaxf(xr * s_scale[kk + kq + 2] + s_shift[kk + kq + 2], 0.f);
                v.w = fmaxf(xr * s_scale[kk + kq + 3] + s_shift[kk + kq + 3], 0.f);
            } else {
                v = *(const float4*)(Xf + (size_t)(r0 + row) * HUU + kk + kq);
                v.x = fmaxf(v.x * s_scale[kk + kq + 0] + s_shift[kk + kq + 0], 0.f);
                v.y = fmaxf(v.y * s_scale[kk + kq + 1] + s_shift[kk + kq + 1], 0.f);
                v.z = fmaxf(v.z * s_scale[kk + kq + 2] + s_shift[kk + kq + 2], 0.f);
                v.w = fmaxf(v.w * s_scale[kk + kq + 3] + s_shift[kk + kq + 3], 0.f);
            }
            As[kq + 0][row] = v.x;  As[kq + 1][row] = v.y;
            As[kq + 2][row] = v.z;  As[kq + 3][row] = v.w;
            Bs[kq + 0][row] = w4.x; Bs[kq + 1][row] = w4.y;
            Bs[kq + 2][row] = w4.z; Bs[kq + 3][row] = w4.w;
        }
        __syncthreads();
#pragma unroll
        for (int k = 0; k < 16; k++) {
            float4 a0 = *(const float4*)&As[k][ty * 8];
            float4 a1 = *(const float4*)&As[k][ty * 8 + 4];
            ulonglong2 bA = *(const ulonglong2*)&Bs[k][tx * 8];
            ulonglong2 bB = *(const ulonglong2*)&Bs[k][tx * 8 + 4];
            float av[8] = {a0.x, a0.y, a0.z, a0.w, a1.x, a1.y, a1.z, a1.w};
            unsigned long long bp[4] = {bA.x, bA.y, bB.x, bB.y};
#pragma unroll
            for (int r = 0; r < 8; r++) {
                unsigned long long ap;
                asm("mov.b64 %0, {%1, %1};" : "=l"(ap) : "f"(av[r]));
#pragma unroll
                for (int c = 0; c < 4; c++)
                    asm("fma.rn.f32x2 %0, %1, %2, %0;" : "+l"(acc[r][c]) : "l"(ap), "l"(bp[c]));
            }
        }
        __syncthreads();
    }

    float lsum[8], lsq[8], bcol[8];
#pragma unroll
    for (int c = 0; c < 8; c++) { lsum[c] = 0.f; lsq[c] = 0.f; bcol[c] = bias[tx * 8 + c]; }
#pragma unroll
    for (int r = 0; r < 8; r++) {
        int row = r0 + ty * 8 + r;
        float y[8];
#pragma unroll
        for (int c = 0; c < 4; c++) {
            float lo, hi;
            asm("mov.b64 {%0, %1}, %2;" : "=f"(lo), "=f"(hi) : "l"(acc[r][c]));
            y[2 * c + 0] = lo + bcol[2 * c + 0];
            y[2 * c + 1] = hi + bcol[2 * c + 1];
        }
#pragma unroll
        for (int c = 0; c < 8; c++) { lsum[c] += y[c]; lsq[c] += y[c] * y[c]; }
        float* dst = Y + ((size_t)f * NN + row) * HUU + tx * 8;
        *(float4*)(dst)     = *(float4*)(y);
        *(float4*)(dst + 4) = *(float4*)(y + 4);
    }
#pragma unroll
    for (int c = 0; c < 8; c++) {
        atomicAdd(&s_sum[tx * 8 + c], lsum[c]);
        atomicAdd(&s_sq[tx * 8 + c],  lsq[c]);
    }
    __syncthreads();
    if (tid < 128) {
        atomicAdd(&out_st[(f * HUU + tid) * 2 + 0], (double)s_sum[tid]);
        atomicAdd(&out_st[(f * HUU + tid) * 2 + 1], (double)s_sq[tid]);
    }
}

__global__ __launch_bounds__(256) void k_out(
        const float* __restrict__ gh, const float* __restrict__ betah,
        const float* __restrict__ Wout, const float* __restrict__ bout) {
    __shared__ float ssc[128], ssh[128], sw[128], rs[256], rq[256];
    int f = blockIdx.y, tid = threadIdx.x;
    if (tid < 128) {
        double mu  = g_st[ST_Y2 + (f * HUU + tid) * 2 + 0] / (double)NN;
        double var = g_st[ST_Y2 + (f * HUU + tid) * 2 + 1] / (double)NN - mu * mu;
        float sc = gh[(f * 2 + 1) * HUU + tid] * rsqrtf((float)var + EPSF);
        ssc[tid] = sc;
        ssh[tid] = betah[(f * 2 + 1) * HUU + tid] - (float)mu * sc;
        sw[tid]  = Wout[f * HUU + tid];
    }
    __syncthreads();
    int n = blockIdx.x * 256 + tid;
    const float* row = g_A + ((size_t)f * NN + n) * HUU;
    float acc = 0.f;
#pragma unroll 8
    for (int k = 0; k < 128; k += 4) {
        float4 v = *(const float4*)(row + k);
        acc += fmaxf(v.x * ssc[k + 0] + ssh[k + 0], 0.f) * sw[k + 0];
        acc += fmaxf(v.y * ssc[k + 1] + ssh[k + 1], 0.f) * sw[k + 1];
        acc += fmaxf(v.z * ssc[k + 2] + ssh[k + 2], 0.f) * sw[k + 2];
        acc += fmaxf(v.w * ssc[k + 3] + ssh[k + 3], 0.f) * sw[k + 3];
    }
    float zv = acc + bout[f];
    g_z[f * NN + n] = zv;
    rs[tid] = zv; rq[tid] = zv * zv;
    __syncthreads();
    for (int o = 128; o > 0; o >>= 1) {
        if (tid < o) { rs[tid] += rs[tid + o]; rq[tid] += rq[tid + o]; }
        __syncthreads();
    }
    if (tid == 0) {
        atomicAdd(&g_st[ST_Z + f * 2 + 0], (double)rs[0]);
        atomicAdd(&g_st[ST_Z + f * 2 + 1], (double)rq[0]);
    }
}

__global__ void k_zaff(const float* __restrict__ gout, const float* __restrict__ betaout) {
    int f = threadIdx.x;
    if (f < FFn) {
        double mu  = g_st[ST_Z + f * 2 + 0] / (double)NN;
        double var = g_st[ST_Z + f * 2 + 1] / (double)NN - mu * mu;
        float sc = gout[f] * rsqrtf((float)var + EPSF);
        g_zaff[f * 2 + 0] = sc;
        g_zaff[f * 2 + 1] = betaout[f] - (float)mu * sc;
    }
}

// fv[l][f][v] += sum_{e in slice} evs(z) * eig[l][e][v];  grid (8 vchunks, 32 l, 4 eslices)
__global__ __launch_bounds__(256) void k_einsum(const float* __restrict__ eig) {
    __shared__ __align__(16) float sh[256 * FFn];
    int l = blockIdx.y;
    int es = blockIdx.z * 256;
    int w = threadIdx.x >> 5, lane = threadIdx.x & 31;
    float zsc = g_zaff[w * 2 + 0], zsh = g_zaff[w * 2 + 1];
    for (int e = lane; e < 256; e += 32)
        sh[e * FFn + w] = fmaxf(g_z[(size_t)w * NN + l * EEn + es + e] * zsc + zsh, 0.f);
    __syncthreads();
    int v = blockIdx.x * 256 + threadIdx.x;
    const float* col = eig + (size_t)l * EEn * VVn + (size_t)es * VVn + v;
    float acc[8] = {0,0,0,0,0,0,0,0};
#pragma unroll 8
    for (int e = 0; e < 256; e++) {
        float ev = col[(size_t)e * VVn];
        float4 a = *(const float4*)(sh + e * FFn);
        float4 b = *(const float4*)(sh + e * FFn + 4);
        acc[0] += a.x * ev; acc[1] += a.y * ev; acc[2] += a.z * ev; acc[3] += a.w * ev;
        acc[4] += b.x * ev; acc[5] += b.y * ev; acc[6] += b.z * ev; acc[7] += b.w * ev;
    }
#pragma unroll
    for (int f = 0; f < 8; f++)
        atomicAdd(&g_fv[((size_t)(l * FFn + f)) * VVn + v], acc[f]);
}

// One block per diagram (l,f,which). Sort 7 projections, then level-3 signature.
__global__ __launch_bounds__(512) void k_diag(
        const int* __restrict__ dgm0, const int* __restrict__ dgm1rel,
        const int* __restrict__ dgm1ext,
        const float* __restrict__ Wproj, const float* __restrict__ bproj) {
    __shared__ float s_srt[7 * 512];
    __shared__ float dxT[8][329];
    __shared__ float s_un[640];
    int d = blockIdx.x;
    int which = d & 1, f = (d >> 1) & 7, l = d >> 4;
    int tid = threadIdx.x;
    int lf = l * FFn + f;
    const float* fvrow = g_fv + (size_t)lf * VVn;
    const float INF = __int_as_float(0x7f800000);

    for (int i = tid; i < 640; i += 512) {
        int col;
        if (which == 0)
            col = (i < 512) ? dgm0[lf * D0C + i] : dgm1rel[lf * D1RC + (640 - i)];
        else
            col = dgm1ext[lf * D1EC + i];
        s_un[i] = fvrow[col];
    }
    __syncthreads();
    for (int t2 = tid; t2 < 7 * 512; t2 += 512) {
        int s = t2 >> 9, p = t2 & 511;
        float v = INF;
        if (p < PPn)
            v = s_un[2 * p] * Wproj[2 * s] + s_un[2 * p + 1] * Wproj[2 * s + 1] + bproj[s];
        s_srt[t2] = v;
    }
    for (int kk = 2; kk <= 512; kk <<= 1) {
        for (int jj = kk >> 1; jj > 0; jj >>= 1) {
            __syncthreads();
            for (int t2 = tid; t2 < 7 * 256; t2 += 512) {
                int row = t2 >> 8, q = t2 & 255;
                int i1 = ((q & ~(jj - 1)) << 1) | (q & (jj - 1));
                int i2 = i1 | jj;
                float* arr = s_srt + (row << 9);
                float a = arr[i1], b = arr[i2];
                if ((a > b) == ((i1 & kk) == 0)) { arr[i1] = b; arr[i2] = a; }
            }
        }
    }
    __syncthreads();
    for (int t2 = tid; t2 < 8 * 319; t2 += 512) {
        int dd = t2 / 319, m = t2 % 319;
        dxT[dd][m] = (dd == 0) ? DT0 : (s_srt[(dd - 1) * 512 + m + 1] - s_srt[(dd - 1) * 512 + m]);
    }
    __syncthreads();

    int i = tid >> 6, j = (tid >> 3) & 7, k = tid & 7;
    float x0 = (i == 0) ? 0.f : s_srt[(i - 1) * 512];
    const float* si_row = (i == 0) ? (const float*)0 : (s_srt + (i - 1) * 512);
    float acc2 = 0.f, acc3 = 0.f;
#pragma unroll 1
    for (int m = 0; m < 319; m++) {
        float dxi = dxT[i][m], dxj = dxT[j][m], dxk = dxT[k][m];
        float s1i = (i == 0) ? ((float)m * DT0) : (si_row[m] - x0);
        float t12 = s1i * dxj;
        acc3 += (acc2 + 0.5f * t12 + (1.0f / 6.0f) * dxi * dxj) * dxk;
        acc2 += t12 + 0.5f * dxi * dxj;
    }

    float* outp = g_x + (size_t)l * FINALC + f * (2 * SIGL) + which * SIGL;
    outp[72 + tid] = acc3;
    if (k == 0) outp[8 + i * 8 + j] = acc2;
    if (tid < 8) {
        float s1;
        if (tid == 0) s1 = 319.f * DT0;
        else s1 = s_srt[(tid - 1) * 512 + 319] - s_srt[(tid - 1) * 512];
        outp[tid] = s1;
    }
}

__global__ void k_final1(const float* __restrict__ Wfin, const float* __restrict__ bfin) {
    __shared__ float rs[256];
    int l = blockIdx.x, tid = threadIdx.x;
    float acc = 0.f;
    for (int idx = tid; idx < FINALC; idx += 256)
        acc += g_x[(size_t)l * FINALC + idx] * Wfin[idx];
    rs[tid] = acc;
    __syncthreads();
    for (int o = 128; o > 0; o >>= 1) {
        if (tid < o) rs[tid] += rs[tid + o];
        __syncthreads();
    }
    if (tid == 0) g_fz[l] = rs[0] + bfin[0];
}

__global__ void k_final2(const float* __restrict__ gfin, const float* __restrict__ befin,
                         float* __restrict__ out) {
    int tid = threadIdx.x;
    float z = g_fz[tid];
    float s = z, q = z * z;
#pragma unroll
    for (int o = 16; o > 0; o >>= 1) {
        s += __shfl_xor_sync(0xffffffff, s, o);
        q += __shfl_xor_sync(0xffffffff, q, o);
    }
    float mu = s / 32.f, var = q / 32.f - mu * mu;
    out[tid] = (z - mu) * rsqrtf(var + EPSF) * gfin[0] + befin[0];
}

extern "C" void kernel_launch(void* const* d_in, const int* in_sizes, int n_in,
                              void* d_out, int out_size) {
    const float* eigenvalues = (const float*)d_in[0];
    const float* eigvec      = (const float*)d_in[1];
    const int*   dgm0        = (const int*)d_in[2];
    const int*   dgm1rel     = (const int*)d_in[3];
    const int*   dgm1ext     = (const int*)d_in[4];
    const float* Win    = (const float*)d_in[5];
    const float* gin    = (const float*)d_in[7];
    const float* bein   = (const float*)d_in[8];
    const float* Wh     = (const float*)d_in[9];
    const float* bh     = (const float*)d_in[10];
    const float* gh     = (const float*)d_in[11];
    const float* betah  = (const float*)d_in[12];
    const float* Wout   = (const float*)d_in[13];
    const float* bout   = (const float*)d_in[14];
    const float* gout   = (const float*)d_in[15];
    const float* betaout= (const float*)d_in[16];
    const float* Wproj  = (const float*)d_in[17];
    const float* bproj  = (const float*)d_in[18];
    const float* Wfin   = (const float*)d_in[19];
    const float* bfin   = (const float*)d_in[20];
    const float* gfin   = (const float*)d_in[21];
    const float* befin  = (const float*)d_in[22];
    float* out = (float*)d_out;

    k_zero<<<2048, 256>>>();
    k_xstats<<<128, 256>>>(eigenvalues);
    k_gemm<<<dim3(256, 1, 8), 256>>>(eigenvalues, Win, gin, bein, Wh, bh, gh, betah, 0, 0);
    k_gemm<<<dim3(256, 1, 8), 256>>>(eigenvalues, Win, gin, bein, Wh, bh, gh, betah, 1, 1);
    k_out<<<dim3(128, 8), 256>>>(gh, betah, Wout, bout);
    k_zaff<<<1, 32>>>(gout, betaout);
    k_einsum<<<dim3(8, 32, 4), 256>>>(eigvec);
    k_diag<<<512, 512>>>(dgm0, dgm1rel, dgm1ext, Wproj, bproj);
    k_final1<<<32, 256>>>(Wfin, bfin);
    k_final2<<<1, 32>>>(gfin, befin, out);
}